// round 10
// baseline (speedup 1.0000x reference)
#include <cuda_runtime.h>
#include <cuda_bf16.h>

// Problem: B=512, S=512, I=64, C=4, H=100, O=7
// out = [output (512*7)] ++ [hidden_states (512*512*100)]

#define ULL unsigned long long

// ---------------- scratch (device globals; no runtime allocation) -----------
__device__ float g_xf[512 * 512 * 100];
__device__ float g_xh[512 * 512 * 100];

// ---------------- helpers ---------------------------------------------------
__device__ __forceinline__ ULL fma2(ULL a, ULL b, ULL c) {
    ULL d;
    asm("fma.rn.f32x2 %0, %1, %2, %3;" : "=l"(d) : "l"(a), "l"(b), "l"(c));
    return d;
}
__device__ __forceinline__ float hsum2(ULL a) {
    float lo, hi;
    asm("mov.b64 {%0,%1}, %2;" : "=f"(lo), "=f"(hi) : "l"(a));
    return lo + hi;
}
__device__ __forceinline__ void unpack2(ULL a, float& lo, float& hi) {
    asm("mov.b64 {%0,%1}, %2;" : "=f"(lo), "=f"(hi) : "l"(a));
}
__device__ __forceinline__ ULL dup2(float v) {
    ULL d;
    asm("mov.b64 %0, {%1,%1};" : "=l"(d) : "f"(v));
    return d;
}
__device__ __forceinline__ float sigmoidf_(float v) {
    return __fdividef(1.f, 1.f + __expf(-v));
}
__device__ __forceinline__ float tanhf_(float v) {
    return 1.f - __fdividef(2.f, __expf(2.f * v) + 1.f);
}

// ---------------- K1: pre-GEMM ----------------------------------------------
// Register-blocked inner loop + shared-transpose coalesced stores.
// 2048 blocks x 256 threads; tile 128 positions x 64 w-rows/pass, 4 passes
// over 200 stacked rows (0..99 = f-gate, 100..199 = h-gate).
// Thread (pg=tid&31, jg=tid>>5): frag = 8 rows (4 j-pair ULLs) x 4 positions.
// Staging pitch 68 floats (multiple of 4 -> float4 accesses stay 16B-aligned;
// the R9 pitch-65 variant faulted on misaligned STS.128). Readout at
// pos*68 + r4*4 is conflict-free (68 mod 32 = 4); staging stores take a 4-way
// conflict but are <5% of shared traffic.
#define PRE_XSF   (64 * 128)               // xs floats
#define PRE_WSF   (64 * 68)                // ws floats
#define PRE_PITCH 68
#define PRE_SHTF  (128 * PRE_PITCH)        // sht floats
#define PRE_CBF   256
#define PRE_SMEM  ((PRE_XSF + PRE_WSF + PRE_SHTF + PRE_CBF) * 4)

__global__ void __launch_bounds__(256, 2)
pre_kernel(const float* __restrict__ x, const float* __restrict__ ctx,
           const float* __restrict__ Wf_w, const float* __restrict__ Wf_b,
           const float* __restrict__ Wh_w, const float* __restrict__ Wh_b)
{
    extern __shared__ float sm[];
    float* xs  = sm;                              // [64][128]  x transposed
    float* ws  = sm + PRE_XSF;                    // [64][68]   w transposed
    float* sht = sm + PRE_XSF + PRE_WSF;          // [128][68]  store staging
    float* cb  = sht + PRE_SHTF;                  // [256]      ctx-folded bias

    const int tid = threadIdx.x;
    const int pg = tid & 31;
    const int jg = tid >> 5;
    const size_t pbase = (size_t)blockIdx.x * 128;

    // ctx-folded bias for all 200 rows (pad rows -> 0)
    {
        int r = tid;
        float v = 0.f;
        if (r < 200) {
            const float* W = (r < 100) ? (Wf_w + r * 168) : (Wh_w + (r - 100) * 168);
            v = (r < 100) ? Wf_b[r] : Wh_b[r - 100];
            #pragma unroll
            for (int c = 0; c < 4; c++) v += ctx[c] * W[64 + c];
        }
        cb[r] = v;
    }

    // load x tile transposed: x[pbase+p][k] -> xs[k][p]
    for (int idx = tid; idx < 2048; idx += 256) {
        int p = idx >> 4, k4 = (idx & 15) << 2;
        float4 v = *(const float4*)(x + (pbase + p) * 64 + k4);
        xs[(k4 + 0) * 128 + p] = v.x;
        xs[(k4 + 1) * 128 + p] = v.y;
        xs[(k4 + 2) * 128 + p] = v.z;
        xs[(k4 + 3) * 128 + p] = v.w;
    }
    __syncthreads();

    #pragma unroll 1
    for (int pass = 0; pass < 4; pass++) {
        // load this pass's 64 rows of weights transposed: W[row][k] -> ws[k][row]
        for (int idx = tid; idx < 1024; idx += 256) {
            int row = idx >> 4, k4 = (idx & 15) << 2;
            int rg = pass * 64 + row;
            int rc = (rg < 200) ? rg : 199;   // clamp (values discarded at store)
            const float* W = (rc < 100) ? (Wf_w + rc * 168) : (Wh_w + (rc - 100) * 168);
            float4 v = *(const float4*)(W + k4);
            ws[(k4 + 0) * 68 + row] = v.x;
            ws[(k4 + 1) * 68 + row] = v.y;
            ws[(k4 + 2) * 68 + row] = v.z;
            ws[(k4 + 3) * 68 + row] = v.w;
        }
        __syncthreads();

        ULL acc[4][4];  // [j-pair][pos]
        #pragma unroll
        for (int a = 0; a < 4; a++)
            #pragma unroll
            for (int b = 0; b < 4; b++) acc[a][b] = 0ull;

        #pragma unroll 8
        for (int k = 0; k < 64; k++) {
            float4 xv = *(const float4*)(xs + k * 128 + pg * 4);
            ulonglong2 wa = *(const ulonglong2*)(ws + k * 68 + jg * 8);
            ulonglong2 wb = *(const ulonglong2*)(ws + k * 68 + jg * 8 + 4);
            ULL x0 = dup2(xv.x), x1 = dup2(xv.y), x2 = dup2(xv.z), x3 = dup2(xv.w);
            acc[0][0] = fma2(wa.x, x0, acc[0][0]);
            acc[0][1] = fma2(wa.x, x1, acc[0][1]);
            acc[0][2] = fma2(wa.x, x2, acc[0][2]);
            acc[0][3] = fma2(wa.x, x3, acc[0][3]);
            acc[1][0] = fma2(wa.y, x0, acc[1][0]);
            acc[1][1] = fma2(wa.y, x1, acc[1][1]);
            acc[1][2] = fma2(wa.y, x2, acc[1][2]);
            acc[1][3] = fma2(wa.y, x3, acc[1][3]);
            acc[2][0] = fma2(wb.x, x0, acc[2][0]);
            acc[2][1] = fma2(wb.x, x1, acc[2][1]);
            acc[2][2] = fma2(wb.x, x2, acc[2][2]);
            acc[2][3] = fma2(wb.x, x3, acc[2][3]);
            acc[3][0] = fma2(wb.y, x0, acc[3][0]);
            acc[3][1] = fma2(wb.y, x1, acc[3][1]);
            acc[3][2] = fma2(wb.y, x2, acc[3][2]);
            acc[3][3] = fma2(wb.y, x3, acc[3][3]);
        }

        // ---- stage frag (+bias) into sht[pos][row-within-pass] -------------
        const int rb = pass * 64 + jg * 8;
        float c0 = cb[rb + 0], c1 = cb[rb + 1], c2 = cb[rb + 2], c3 = cb[rb + 3];
        float c4 = cb[rb + 4], c5 = cb[rb + 5], c6 = cb[rb + 6], c7 = cb[rb + 7];
        #pragma unroll
        for (int i = 0; i < 4; i++) {
            int p = pg * 4 + i;
            float v0, v1, v2, v3, v4, v5, v6, v7;
            unpack2(acc[0][i], v0, v1);
            unpack2(acc[1][i], v2, v3);
            unpack2(acc[2][i], v4, v5);
            unpack2(acc[3][i], v6, v7);
            *(float4*)&sht[p * PRE_PITCH + jg * 8] =
                make_float4(v0 + c0, v1 + c1, v2 + c2, v3 + c3);
            *(float4*)&sht[p * PRE_PITCH + jg * 8 + 4] =
                make_float4(v4 + c4, v5 + c5, v6 + c6, v7 + c7);
        }
        __syncthreads();

        // ---- coalesced store: per pos, 64 consecutive rows (256B runs) -----
        for (int f = tid; f < 2048; f += 256) {
            int pos = f >> 4, r4 = f & 15;
            int rg4 = pass * 64 + r4 * 4;     // multiple of 4: never straddles 100
            float4 v = *(const float4*)&sht[pos * PRE_PITCH + r4 * 4];
            size_t po = (pbase + pos) * 100;
            if (rg4 < 100)       *(float4*)(g_xf + po + rg4)       = v;
            else if (rg4 < 200)  *(float4*)(g_xh + po + rg4 - 100) = v;
        }
        __syncthreads();  // ws/sht reused next pass
    }
}

// ---------------- K2: sequential scan (R4 structure, known-good) -------------
// 128 blocks x 4 batch rows x 400 threads: thread (j = tid%100, c = tid/100).
// Matvecs: chunk c covers k in [28c, 28c+28) (padded to 112 with zeros).
// Activation/update: thread (j,c) owns row r=c -> all threads busy.
__global__ void __launch_bounds__(400, 1)
scan_kernel(const float* __restrict__ Wf_w, const float* __restrict__ Wh_w,
            float* __restrict__ hidden)
{
    const int tid = threadIdx.x;
    const int c = tid / 100;
    const int j = tid - c * 100;
    const int kb = 28 * c;
    const int rbase = blockIdx.x * 4;

    __shared__ __align__(16) float sh_h[4][112];
    __shared__ __align__(16) float sh_fh[4][112];
    __shared__ __align__(16) float4 sh_p[4][100];  // [chunk][j] partials (4 rows)

    ULL wf2[14], wh2[14];
    {
        const int lc = (c == 3) ? 8 : 14;
        const ULL* pf = (const ULL*)(Wf_w + j * 168 + 68 + kb);
        const ULL* ph = (const ULL*)(Wh_w + j * 168 + 68 + kb);
        #pragma unroll
        for (int t = 0; t < 14; t++) {
            wf2[t] = (t < lc) ? pf[t] : 0ull;
            wh2[t] = (t < lc) ? ph[t] : 0ull;
        }
    }

    for (int idx = tid; idx < 4 * 112; idx += 400) {
        (&sh_h[0][0])[idx]  = 0.f;
        (&sh_fh[0][0])[idx] = 0.f;
    }
    __syncthreads();

    const int r = c;
    const size_t xbase = (size_t)(rbase + r) * 51200 + j;
    float xf_cur = g_xf[xbase];
    float xh_cur = g_xh[xbase];
    float xf_nxt = 0.f, xh_nxt = 0.f, fg = 0.f, hold = 0.f;

    #pragma unroll 1
    for (int s = 0; s < 512; s++) {
        // -- matvec 1: Wf_h . h
        {
            ULL a0 = 0ull, a1 = 0ull, a2 = 0ull, a3 = 0ull;
            #pragma unroll
            for (int t = 0; t < 7; t++) {
                ulonglong2 h0 = *(const ulonglong2*)&sh_h[0][kb + 4 * t];
                ulonglong2 h1 = *(const ulonglong2*)&sh_h[1][kb + 4 * t];
                ulonglong2 h2 = *(const ulonglong2*)&sh_h[2][kb + 4 * t];
                ulonglong2 h3 = *(const ulonglong2*)&sh_h[3][kb + 4 * t];
                a0 = fma2(wf2[2 * t], h0.x, a0); a0 = fma2(wf2[2 * t + 1], h0.y, a0);
                a1 = fma2(wf2[2 * t], h1.x, a1); a1 = fma2(wf2[2 * t + 1], h1.y, a1);
                a2 = fma2(wf2[2 * t], h2.x, a2); a2 = fma2(wf2[2 * t + 1], h2.y, a2);
                a3 = fma2(wf2[2 * t], h3.x, a3); a3 = fma2(wf2[2 * t + 1], h3.y, a3);
            }
            sh_p[c][j] = make_float4(hsum2(a0), hsum2(a1), hsum2(a2), hsum2(a3));
        }
        __syncthreads();  // (1)

        // -- act 1: f-gate, f*h
        {
            float4 p0 = sh_p[0][j], p1 = sh_p[1][j], p2 = sh_p[2][j], p3 = sh_p[3][j];
            const float* q0 = (const float*)&p0;
            const float* q1 = (const float*)&p1;
            const float* q2 = (const float*)&p2;
            const float* q3 = (const float*)&p3;
            float sum = q0[r] + q1[r] + q2[r] + q3[r];
            fg = sigmoidf_(sum + xf_cur);
            hold = sh_h[r][j];
            sh_fh[r][j] = fg * hold;
            int sp = (s < 511) ? s + 1 : 511;
            xf_nxt = g_xf[xbase + (size_t)sp * 100];
            xh_nxt = g_xh[xbase + (size_t)sp * 100];
        }
        __syncthreads();  // (2)

        // -- matvec 2: Wh_h . (f*h)
        {
            ULL a0 = 0ull, a1 = 0ull, a2 = 0ull, a3 = 0ull;
            #pragma unroll
            for (int t = 0; t < 7; t++) {
                ulonglong2 h0 = *(const ulonglong2*)&sh_fh[0][kb + 4 * t];
                ulonglong2 h1 = *(const ulonglong2*)&sh_fh[1][kb + 4 * t];
                ulonglong2 h2 = *(const ulonglong2*)&sh_fh[2][kb + 4 * t];
                ulonglong2 h3 = *(const ulonglong2*)&sh_fh[3][kb + 4 * t];
                a0 = fma2(wh2[2 * t], h0.x, a0); a0 = fma2(wh2[2 * t + 1], h0.y, a0);
                a1 = fma2(wh2[2 * t], h1.x, a1); a1 = fma2(wh2[2 * t + 1], h1.y, a1);
                a2 = fma2(wh2[2 * t], h2.x, a2); a2 = fma2(wh2[2 * t + 1], h2.y, a2);
                a3 = fma2(wh2[2 * t], h3.x, a3); a3 = fma2(wh2[2 * t + 1], h3.y, a3);
            }
            sh_p[c][j] = make_float4(hsum2(a0), hsum2(a1), hsum2(a2), hsum2(a3));
        }
        __syncthreads();  // (3)

        // -- act 2: h update + store
        {
            float4 p0 = sh_p[0][j], p1 = sh_p[1][j], p2 = sh_p[2][j], p3 = sh_p[3][j];
            const float* q0 = (const float*)&p0;
            const float* q1 = (const float*)&p1;
            const float* q2 = (const float*)&p2;
            const float* q3 = (const float*)&p3;
            float sum = q0[r] + q1[r] + q2[r] + q3[r];
            float ht = tanhf_(sum + xh_cur);
            float hn = hold + fg * (ht - hold);
            sh_h[r][j] = hn;
            hidden[((size_t)(rbase + r) * 512 + s) * 100 + j] = hn;
            xf_cur = xf_nxt;
            xh_cur = xh_nxt;
        }
        __syncthreads();  // (4)
    }
}

// ---------------- K3: output head (warp per output) --------------------------
__global__ void head_kernel(const float* __restrict__ hidden,
                            const float* __restrict__ ro_w,
                            const float* __restrict__ ro_b,
                            float* __restrict__ out)
{
    int warp = (blockIdx.x * blockDim.x + threadIdx.x) >> 5;
    int lane = threadIdx.x & 31;
    if (warp >= 512 * 7) return;
    int b = warp / 7, o = warp - b * 7;
    const float* h = hidden + ((size_t)b * 512 + 511) * 100;
    const float* w = ro_w + o * 100;
    float acc = 0.f;
    for (int k = lane; k < 100; k += 32) acc += h[k] * w[k];
    #pragma unroll
    for (int d = 16; d; d >>= 1) acc += __shfl_xor_sync(0xFFFFFFFFu, acc, d);
    if (lane == 0) out[b * 7 + o] = acc + ro_b[o];
}

// ---------------- launch -----------------------------------------------------
extern "C" void kernel_launch(void* const* d_in, const int* in_sizes, int n_in,
                              void* d_out, int out_size)
{
    (void)in_sizes; (void)n_in; (void)out_size;
    const float* x     = (const float*)d_in[0];
    const float* ctx   = (const float*)d_in[1];
    const float* Wf_w  = (const float*)d_in[2];
    const float* Wf_b  = (const float*)d_in[3];
    const float* Wh_w  = (const float*)d_in[4];
    const float* Wh_b  = (const float*)d_in[5];
    const float* ro_w  = (const float*)d_in[6];
    const float* ro_b  = (const float*)d_in[7];

    float* out    = (float*)d_out;
    float* hidden = out + 512 * 7;

    cudaFuncSetAttribute(pre_kernel,
                         cudaFuncAttributeMaxDynamicSharedMemorySize, PRE_SMEM);
    pre_kernel<<<2048, 256, PRE_SMEM>>>(x, ctx, Wf_w, Wf_b, Wh_w, Wh_b);
    scan_kernel<<<128, 400>>>(Wf_w, Wh_w, hidden);
    head_kernel<<<448, 256>>>(hidden, ro_w, ro_b, out);
}

// round 11
// speedup vs baseline: 1.3634x; 1.3634x over previous
#include <cuda_runtime.h>
#include <cuda_bf16.h>

// Problem: B=512, S=512, I=64, C=4, H=100, O=7
// out = [output (512*7)] ++ [hidden_states (512*512*100)]

#define ULL unsigned long long

// ---------------- scratch (device globals; no runtime allocation) -----------
__device__ float g_xf[512 * 512 * 100];
__device__ float g_xh[512 * 512 * 100];

// ---------------- helpers ---------------------------------------------------
__device__ __forceinline__ ULL fma2(ULL a, ULL b, ULL c) {
    ULL d;
    asm("fma.rn.f32x2 %0, %1, %2, %3;" : "=l"(d) : "l"(a), "l"(b), "l"(c));
    return d;
}
__device__ __forceinline__ float hsum2(ULL a) {
    float lo, hi;
    asm("mov.b64 {%0,%1}, %2;" : "=f"(lo), "=f"(hi) : "l"(a));
    return lo + hi;
}
__device__ __forceinline__ void unpack2(ULL a, float& lo, float& hi) {
    asm("mov.b64 {%0,%1}, %2;" : "=f"(lo), "=f"(hi) : "l"(a));
}
__device__ __forceinline__ ULL dup2(float v) {
    ULL d;
    asm("mov.b64 %0, {%1,%1};" : "=l"(d) : "f"(v));
    return d;
}
__device__ __forceinline__ float sigmoidf_(float v) {
    return __fdividef(1.f, 1.f + __expf(-v));
}
__device__ __forceinline__ float tanhf_(float v) {
    return 1.f - __fdividef(2.f, __expf(2.f * v) + 1.f);
}

// ---------------- K1: pre-GEMM (8x8 register fragments) ----------------------
// 2048 blocks x 128 threads; tile 128 positions x 64 w-rows/pass, 4 passes
// over 200 stacked rows (0..99 = f-gate, 100..199 = h-gate).
// Thread (pg=tid&15, jg=tid>>4): frag = 8 rows (4 j-pair ULLs) x 8 positions.
// Doubling positions/thread halves LDS wavefronts per fma (prior versions
// were L1tex-wavefront bound at ~85%).
#define PRE_XSF   (64 * 128)               // xs floats
#define PRE_WSF   (64 * 68)                // ws floats
#define PRE_PITCH 68                       // multiple of 4: float4 aligned
#define PRE_SHTF  (128 * PRE_PITCH)        // sht floats
#define PRE_CBF   256
#define PRE_SMEM  ((PRE_XSF + PRE_WSF + PRE_SHTF + PRE_CBF) * 4)

__global__ void __launch_bounds__(128, 2)
pre_kernel(const float* __restrict__ x, const float* __restrict__ ctx,
           const float* __restrict__ Wf_w, const float* __restrict__ Wf_b,
           const float* __restrict__ Wh_w, const float* __restrict__ Wh_b)
{
    extern __shared__ float sm[];
    float* xs  = sm;                              // [64][128]  x transposed
    float* ws  = sm + PRE_XSF;                    // [64][68]   w transposed
    float* sht = sm + PRE_XSF + PRE_WSF;          // [128][68]  store staging
    float* cb  = sht + PRE_SHTF;                  // [256]      ctx-folded bias

    const int tid = threadIdx.x;
    const int pg = tid & 15;
    const int jg = tid >> 4;
    const size_t pbase = (size_t)blockIdx.x * 128;

    // ctx-folded bias for all 200 rows (pad rows -> 0)
    for (int r = tid; r < 256; r += 128) {
        float v = 0.f;
        if (r < 200) {
            const float* W = (r < 100) ? (Wf_w + r * 168) : (Wh_w + (r - 100) * 168);
            v = (r < 100) ? Wf_b[r] : Wh_b[r - 100];
            #pragma unroll
            for (int c = 0; c < 4; c++) v += ctx[c] * W[64 + c];
        }
        cb[r] = v;
    }

    // load x tile transposed: x[pbase+p][k] -> xs[k][p]
    for (int idx = tid; idx < 2048; idx += 128) {
        int p = idx >> 4, k4 = (idx & 15) << 2;
        float4 v = *(const float4*)(x + (pbase + p) * 64 + k4);
        xs[(k4 + 0) * 128 + p] = v.x;
        xs[(k4 + 1) * 128 + p] = v.y;
        xs[(k4 + 2) * 128 + p] = v.z;
        xs[(k4 + 3) * 128 + p] = v.w;
    }
    __syncthreads();

    #pragma unroll 1
    for (int pass = 0; pass < 4; pass++) {
        // load this pass's 64 rows of weights transposed: W[row][k] -> ws[k][row]
        for (int idx = tid; idx < 1024; idx += 128) {
            int row = idx >> 4, k4 = (idx & 15) << 2;
            int rg = pass * 64 + row;
            int rc = (rg < 200) ? rg : 199;   // clamp (values discarded at store)
            const float* W = (rc < 100) ? (Wf_w + rc * 168) : (Wh_w + (rc - 100) * 168);
            float4 v = *(const float4*)(W + k4);
            ws[(k4 + 0) * 68 + row] = v.x;
            ws[(k4 + 1) * 68 + row] = v.y;
            ws[(k4 + 2) * 68 + row] = v.z;
            ws[(k4 + 3) * 68 + row] = v.w;
        }
        __syncthreads();

        ULL acc[4][8];  // [j-pair][pos]
        #pragma unroll
        for (int a = 0; a < 4; a++)
            #pragma unroll
            for (int b = 0; b < 8; b++) acc[a][b] = 0ull;

        #pragma unroll 2
        for (int k = 0; k < 64; k++) {
            float4 xv0 = *(const float4*)(xs + k * 128 + pg * 8);
            float4 xv1 = *(const float4*)(xs + k * 128 + pg * 8 + 4);
            ulonglong2 wa = *(const ulonglong2*)(ws + k * 68 + jg * 8);
            ulonglong2 wb = *(const ulonglong2*)(ws + k * 68 + jg * 8 + 4);
            ULL xd[8];
            xd[0] = dup2(xv0.x); xd[1] = dup2(xv0.y);
            xd[2] = dup2(xv0.z); xd[3] = dup2(xv0.w);
            xd[4] = dup2(xv1.x); xd[5] = dup2(xv1.y);
            xd[6] = dup2(xv1.z); xd[7] = dup2(xv1.w);
            #pragma unroll
            for (int i = 0; i < 8; i++) {
                acc[0][i] = fma2(wa.x, xd[i], acc[0][i]);
                acc[1][i] = fma2(wa.y, xd[i], acc[1][i]);
                acc[2][i] = fma2(wb.x, xd[i], acc[2][i]);
                acc[3][i] = fma2(wb.y, xd[i], acc[3][i]);
            }
        }

        // ---- stage frag (+bias) into sht[pos][row-within-pass] -------------
        const int rb = pass * 64 + jg * 8;
        float c0 = cb[rb + 0], c1 = cb[rb + 1], c2 = cb[rb + 2], c3 = cb[rb + 3];
        float c4 = cb[rb + 4], c5 = cb[rb + 5], c6 = cb[rb + 6], c7 = cb[rb + 7];
        #pragma unroll
        for (int i = 0; i < 8; i++) {
            int p = pg * 8 + i;
            float v0, v1, v2, v3, v4, v5, v6, v7;
            unpack2(acc[0][i], v0, v1);
            unpack2(acc[1][i], v2, v3);
            unpack2(acc[2][i], v4, v5);
            unpack2(acc[3][i], v6, v7);
            *(float4*)&sht[p * PRE_PITCH + jg * 8] =
                make_float4(v0 + c0, v1 + c1, v2 + c2, v3 + c3);
            *(float4*)&sht[p * PRE_PITCH + jg * 8 + 4] =
                make_float4(v4 + c4, v5 + c5, v6 + c6, v7 + c7);
        }
        __syncthreads();

        // ---- coalesced store: per pos, 64 consecutive rows (256B runs) -----
        for (int f = tid; f < 2048; f += 128) {
            int pos = f >> 4, r4 = f & 15;
            int rg4 = pass * 64 + r4 * 4;     // multiple of 4: never straddles 100
            float4 v = *(const float4*)&sht[pos * PRE_PITCH + r4 * 4];
            size_t po = (pbase + pos) * 100;
            if (rg4 < 100)       *(float4*)(g_xf + po + rg4)       = v;
            else if (rg4 < 200)  *(float4*)(g_xh + po + rg4 - 100) = v;
        }
        __syncthreads();  // ws/sht reused next pass
    }
}

// ---------------- K2: sequential scan (exact R4 known-good version) ----------
// 128 blocks x 4 batch rows x 400 threads: thread (j = tid%100, c = tid/100).
// Matvecs: chunk c covers k in [28c, 28c+28) (padded to 112 with zeros).
// Activation/update: thread (j,c) owns row r=c; partials read as scalar
// dynamic-index SHARED loads (a float4 register copy indexed by runtime r
// goes to local memory — that was the R9/R10 scan regression).
__global__ void __launch_bounds__(400, 1)
scan_kernel(const float* __restrict__ Wf_w, const float* __restrict__ Wh_w,
            float* __restrict__ hidden)
{
    const int tid = threadIdx.x;
    const int c = tid / 100;
    const int j = tid - c * 100;
    const int kb = 28 * c;
    const int rbase = blockIdx.x * 4;

    __shared__ __align__(16) float sh_h[4][112];
    __shared__ __align__(16) float sh_fh[4][112];
    __shared__ __align__(16) float sh_p[4][100][4];  // [chunk][j][row]

    ULL wf2[14], wh2[14];
    {
        const int lc = (c == 3) ? 8 : 14;
        const ULL* pf = (const ULL*)(Wf_w + j * 168 + 68 + kb);
        const ULL* ph = (const ULL*)(Wh_w + j * 168 + 68 + kb);
        #pragma unroll
        for (int t = 0; t < 14; t++) {
            wf2[t] = (t < lc) ? pf[t] : 0ull;
            wh2[t] = (t < lc) ? ph[t] : 0ull;
        }
    }

    for (int idx = tid; idx < 4 * 112; idx += 400) {
        (&sh_h[0][0])[idx]  = 0.f;
        (&sh_fh[0][0])[idx] = 0.f;
    }
    __syncthreads();

    const int r = c;
    const size_t xbase = (size_t)(rbase + r) * 51200 + j;
    float xf_cur = g_xf[xbase];
    float xh_cur = g_xh[xbase];
    float xf_nxt = 0.f, xh_nxt = 0.f, fg = 0.f, hold = 0.f;

    #pragma unroll 1
    for (int s = 0; s < 512; s++) {
        // -- matvec 1: Wf_h . h
        {
            ULL a0 = 0ull, a1 = 0ull, a2 = 0ull, a3 = 0ull;
            #pragma unroll
            for (int t = 0; t < 7; t++) {
                ulonglong2 h0 = *(const ulonglong2*)&sh_h[0][kb + 4 * t];
                ulonglong2 h1 = *(const ulonglong2*)&sh_h[1][kb + 4 * t];
                ulonglong2 h2 = *(const ulonglong2*)&sh_h[2][kb + 4 * t];
                ulonglong2 h3 = *(const ulonglong2*)&sh_h[3][kb + 4 * t];
                a0 = fma2(wf2[2 * t], h0.x, a0); a0 = fma2(wf2[2 * t + 1], h0.y, a0);
                a1 = fma2(wf2[2 * t], h1.x, a1); a1 = fma2(wf2[2 * t + 1], h1.y, a1);
                a2 = fma2(wf2[2 * t], h2.x, a2); a2 = fma2(wf2[2 * t + 1], h2.y, a2);
                a3 = fma2(wf2[2 * t], h3.x, a3); a3 = fma2(wf2[2 * t + 1], h3.y, a3);
            }
            *(float4*)&sh_p[c][j][0] =
                make_float4(hsum2(a0), hsum2(a1), hsum2(a2), hsum2(a3));
        }
        __syncthreads();  // (1)

        // -- act 1: f-gate, f*h
        {
            float sum = sh_p[0][j][r] + sh_p[1][j][r] + sh_p[2][j][r] + sh_p[3][j][r];
            fg = sigmoidf_(sum + xf_cur);
            hold = sh_h[r][j];
            sh_fh[r][j] = fg * hold;
            int sp = (s < 511) ? s + 1 : 511;
            xf_nxt = g_xf[xbase + (size_t)sp * 100];
            xh_nxt = g_xh[xbase + (size_t)sp * 100];
        }
        __syncthreads();  // (2)

        // -- matvec 2: Wh_h . (f*h)
        {
            ULL a0 = 0ull, a1 = 0ull, a2 = 0ull, a3 = 0ull;
            #pragma unroll
            for (int t = 0; t < 7; t++) {
                ulonglong2 h0 = *(const ulonglong2*)&sh_fh[0][kb + 4 * t];
                ulonglong2 h1 = *(const ulonglong2*)&sh_fh[1][kb + 4 * t];
                ulonglong2 h2 = *(const ulonglong2*)&sh_fh[2][kb + 4 * t];
                ulonglong2 h3 = *(const ulonglong2*)&sh_fh[3][kb + 4 * t];
                a0 = fma2(wh2[2 * t], h0.x, a0); a0 = fma2(wh2[2 * t + 1], h0.y, a0);
                a1 = fma2(wh2[2 * t], h1.x, a1); a1 = fma2(wh2[2 * t + 1], h1.y, a1);
                a2 = fma2(wh2[2 * t], h2.x, a2); a2 = fma2(wh2[2 * t + 1], h2.y, a2);
                a3 = fma2(wh2[2 * t], h3.x, a3); a3 = fma2(wh2[2 * t + 1], h3.y, a3);
            }
            *(float4*)&sh_p[c][j][0] =
                make_float4(hsum2(a0), hsum2(a1), hsum2(a2), hsum2(a3));
        }
        __syncthreads();  // (3)

        // -- act 2: h update + store
        {
            float sum = sh_p[0][j][r] + sh_p[1][j][r] + sh_p[2][j][r] + sh_p[3][j][r];
            float ht = tanhf_(sum + xh_cur);
            float hn = hold + fg * (ht - hold);
            sh_h[r][j] = hn;
            hidden[((size_t)(rbase + r) * 512 + s) * 100 + j] = hn;
            xf_cur = xf_nxt;
            xh_cur = xh_nxt;
        }
        __syncthreads();  // (4)
    }
}

// ---------------- K3: output head (warp per output) --------------------------
__global__ void head_kernel(const float* __restrict__ hidden,
                            const float* __restrict__ ro_w,
                            const float* __restrict__ ro_b,
                            float* __restrict__ out)
{
    int warp = (blockIdx.x * blockDim.x + threadIdx.x) >> 5;
    int lane = threadIdx.x & 31;
    if (warp >= 512 * 7) return;
    int b = warp / 7, o = warp - b * 7;
    const float* h = hidden + ((size_t)b * 512 + 511) * 100;
    const float* w = ro_w + o * 100;
    float acc = 0.f;
    for (int k = lane; k < 100; k += 32) acc += h[k] * w[k];
    #pragma unroll
    for (int d = 16; d; d >>= 1) acc += __shfl_xor_sync(0xFFFFFFFFu, acc, d);
    if (lane == 0) out[b * 7 + o] = acc + ro_b[o];
}

// ---------------- launch -----------------------------------------------------
extern "C" void kernel_launch(void* const* d_in, const int* in_sizes, int n_in,
                              void* d_out, int out_size)
{
    (void)in_sizes; (void)n_in; (void)out_size;
    const float* x     = (const float*)d_in[0];
    const float* ctx   = (const float*)d_in[1];
    const float* Wf_w  = (const float*)d_in[2];
    const float* Wf_b  = (const float*)d_in[3];
    const float* Wh_w  = (const float*)d_in[4];
    const float* Wh_b  = (const float*)d_in[5];
    const float* ro_w  = (const float*)d_in[6];
    const float* ro_b  = (const float*)d_in[7];

    float* out    = (float*)d_out;
    float* hidden = out + 512 * 7;

    cudaFuncSetAttribute(pre_kernel,
                         cudaFuncAttributeMaxDynamicSharedMemorySize, PRE_SMEM);
    pre_kernel<<<2048, 128, PRE_SMEM>>>(x, ctx, Wf_w, Wf_b, Wh_w, Wh_b);
    scan_kernel<<<128, 400>>>(Wf_w, Wh_w, hidden);
    head_kernel<<<448, 256>>>(hidden, ro_w, ro_b, out);
}